// round 1
// baseline (speedup 1.0000x reference)
#include <cuda_runtime.h>

typedef unsigned long long ull;

#define BATCH 512
#define SEQ_S 1024
#define SEQ_T 512
#define HID   64
#define G4    256
#define R     4
#define NBLK  (BATCH / R)   // 128 CTAs

// Scratch (device globals: allocation-free rule)
static __device__ float g_y1[(size_t)BATCH * SEQ_S * HID]; // enc1 outputs, 128 MB
static __device__ float g_h[BATCH * HID];
static __device__ float g_c[BATCH * HID];

__device__ __forceinline__ ull pack2(float x, float y) {
    ull r; asm("mov.b64 %0, {%1, %2};" : "=l"(r) : "f"(x), "f"(y)); return r;
}
__device__ __forceinline__ void fma2(ull &acc, ull a, ull b) {
    asm("fma.rn.f32x2 %0, %1, %2, %0;" : "+l"(acc) : "l"(a), "l"(b));
}
__device__ __forceinline__ float hsum(ull a) {
    float x, y; asm("mov.b64 {%0, %1}, %2;" : "=f"(x), "=f"(y) : "l"(a));
    return x + y;
}
__device__ __forceinline__ float sigm(float x) { return 1.0f / (1.0f + __expf(-x)); }
__device__ __forceinline__ float tanh_f(float x) {
    float e = __expf(-2.0f * fabsf(x));
    float r = (1.0f - e) / (1.0f + e);
    return copysignf(r, x);
}

// ---------------------------------------------------------------------------
// Encoder layer 1: x (3-dim) -> y1, all 1024 steps. One thread per gate,
// weights in registers, h broadcast via smem.
// ---------------------------------------------------------------------------
__global__ void __launch_bounds__(256, 1)
k_enc1(const float* __restrict__ src, const float* __restrict__ Wih,
       const float* __restrict__ Whh, const float* __restrict__ bias)
{
    __shared__ __align__(16) float hs[R][HID];
    __shared__ __align__(16) float xs[R][4];
    __shared__ float gact[R][G4];

    const int g  = threadIdx.x;
    const int b0 = blockIdx.x * R;
    const int jj = g & 63, rr = g >> 6;
    const int wg = g >> 6;   // gate group: 0=i,1=f,2=g,3=o (warp-uniform)

    ull wx0, wx1;
    {
        float w0 = Wih[g*3+0], w1 = Wih[g*3+1], w2 = Wih[g*3+2];
        wx0 = pack2(w0, w1); wx1 = pack2(w2, 0.0f);
    }
    ull wh[32];
#pragma unroll
    for (int k = 0; k < 32; k++)
        wh[k] = pack2(Whh[g*HID + 2*k], Whh[g*HID + 2*k + 1]);
    const float bb = bias[g];

    float c = 0.0f;
    hs[rr][jj] = 0.0f;
    {
        int pr = g >> 2, pd = g & 3;
        if (g < R*4) xs[pr][pd] = (pd < 3) ? src[((size_t)(b0+pr)*SEQ_S + 0)*3 + pd] : 0.0f;
    }
    __syncthreads();

    for (int t = 0; t < SEQ_S; t++) {
        // prefetch next-step x into registers (hidden under the FMA block)
        float xpf = 0.0f;
        const int pr = g >> 2, pd = g & 3;
        if (g < R*4 && pd < 3 && (t+1) < SEQ_S)
            xpf = src[((size_t)(b0+pr)*SEQ_S + (t+1))*3 + pd];

        ull acc[R];
#pragma unroll
        for (int r = 0; r < R; r++) {
            const ull* xv = (const ull*)(&xs[r][0]);
            acc[r] = 0ull;
            fma2(acc[r], wx0, xv[0]);
            fma2(acc[r], wx1, xv[1]);
        }
#pragma unroll
        for (int k = 0; k < 16; k++) {
#pragma unroll
            for (int r = 0; r < R; r++) {
                ulonglong2 p = ((const ulonglong2*)(&hs[r][0]))[k];
                fma2(acc[r], wh[2*k],   p.x);
                fma2(acc[r], wh[2*k+1], p.y);
            }
        }
#pragma unroll
        for (int r = 0; r < R; r++) {
            float v = hsum(acc[r]) + bb;
            gact[r][g] = (wg == 2) ? tanh_f(v) : sigm(v);
        }
        __syncthreads();
        {
            float si = gact[rr][jj], sf = gact[rr][64+jj];
            float tg = gact[rr][128+jj], so = gact[rr][192+jj];
            c = sf * c + si * tg;
            float h = so * tanh_f(c);
            hs[rr][jj] = h;
            g_y1[((size_t)(b0+rr)*SEQ_S + t)*HID + jj] = h;
        }
        if (g < R*4 && pd < 3) xs[pr][pd] = xpf;
        __syncthreads();
    }
}

// ---------------------------------------------------------------------------
// Encoder layer 2: x = y1 (64-dim). Writes final (h, c) for the decoder.
// ---------------------------------------------------------------------------
__global__ void __launch_bounds__(256, 1)
k_enc2(const float* __restrict__ Wih, const float* __restrict__ Whh,
       const float* __restrict__ bias)
{
    __shared__ __align__(16) float hs[R][HID];
    __shared__ __align__(16) float xsh[R][HID];
    __shared__ float gact[R][G4];

    const int g  = threadIdx.x;
    const int b0 = blockIdx.x * R;
    const int jj = g & 63, rr = g >> 6;
    const int wg = g >> 6;

    ull wx[32], wh[32];
#pragma unroll
    for (int k = 0; k < 32; k++) {
        wx[k] = pack2(Wih[g*HID + 2*k], Wih[g*HID + 2*k + 1]);
        wh[k] = pack2(Whh[g*HID + 2*k], Whh[g*HID + 2*k + 1]);
    }
    const float bb = bias[g];

    float c = 0.0f;
    hs[rr][jj]  = 0.0f;
    xsh[rr][jj] = g_y1[((size_t)(b0+rr)*SEQ_S + 0)*HID + jj];
    __syncthreads();

    for (int t = 0; t < SEQ_S; t++) {
        float xpf = 0.0f;
        if (t+1 < SEQ_S)
            xpf = g_y1[((size_t)(b0+rr)*SEQ_S + (t+1))*HID + jj];

        ull acc[R];
#pragma unroll
        for (int r = 0; r < R; r++) acc[r] = 0ull;
#pragma unroll
        for (int k = 0; k < 16; k++) {
#pragma unroll
            for (int r = 0; r < R; r++) {
                ulonglong2 px = ((const ulonglong2*)(&xsh[r][0]))[k];
                fma2(acc[r], wx[2*k],   px.x);
                fma2(acc[r], wx[2*k+1], px.y);
                ulonglong2 ph = ((const ulonglong2*)(&hs[r][0]))[k];
                fma2(acc[r], wh[2*k],   ph.x);
                fma2(acc[r], wh[2*k+1], ph.y);
            }
        }
#pragma unroll
        for (int r = 0; r < R; r++) {
            float v = hsum(acc[r]) + bb;
            gact[r][g] = (wg == 2) ? tanh_f(v) : sigm(v);
        }
        __syncthreads();
        {
            float si = gact[rr][jj], sf = gact[rr][64+jj];
            float tg = gact[rr][128+jj], so = gact[rr][192+jj];
            c = sf * c + si * tg;
            hs[rr][jj]  = so * tanh_f(c);
            xsh[rr][jj] = xpf;
        }
        __syncthreads();
    }
    g_h[(b0+rr)*HID + jj] = hs[rr][jj];
    g_c[(b0+rr)*HID + jj] = c;
}

// ---------------------------------------------------------------------------
// Decoder: 511 steps, dec1 (x=trg[t]) then dec2 with x=h=h1 -> merged weights
// Wd2 = Wih2 + Whh2 (K=64 instead of 128). fc epilogue on 12 threads.
// ---------------------------------------------------------------------------
__global__ void __launch_bounds__(256, 1)
k_dec(const float* __restrict__ trg,
      const float* __restrict__ W1i, const float* __restrict__ W1h, const float* __restrict__ b1,
      const float* __restrict__ W2i, const float* __restrict__ W2h, const float* __restrict__ b2,
      const float* __restrict__ fcW, const float* __restrict__ fcb,
      float* __restrict__ out)
{
    __shared__ __align__(16) float hs[R][HID];
    __shared__ __align__(16) float h1s[R][HID];
    __shared__ __align__(16) float xs[R][4];
    __shared__ float gact[R][G4];
    __shared__ float fcWs[3*HID];
    __shared__ float fcbs[3];

    const int g  = threadIdx.x;
    const int b0 = blockIdx.x * R;
    const int jj = g & 63, rr = g >> 6;
    const int wg = g >> 6;

    ull wx0, wx1;
    {
        float w0 = W1i[g*3+0], w1 = W1i[g*3+1], w2 = W1i[g*3+2];
        wx0 = pack2(w0, w1); wx1 = pack2(w2, 0.0f);
    }
    ull wh1[32], wd2[32];
#pragma unroll
    for (int k = 0; k < 32; k++) {
        wh1[k] = pack2(W1h[g*HID+2*k], W1h[g*HID+2*k+1]);
        wd2[k] = pack2(W2i[g*HID+2*k]   + W2h[g*HID+2*k],
                       W2i[g*HID+2*k+1] + W2h[g*HID+2*k+1]);
    }
    const float bb1 = b1[g], bb2 = b2[g];

    if (g < 3*HID) fcWs[g] = fcW[g];
    if (g < 3)     fcbs[g] = fcb[g];

    float c = g_c[(b0+rr)*HID + jj];
    hs[rr][jj] = g_h[(b0+rr)*HID + jj];
    {
        int pr = g >> 2, pd = g & 3;
        if (g < R*4) xs[pr][pd] = (pd < 3) ? trg[((size_t)(b0+pr)*SEQ_T + 0)*3 + pd] : 0.0f;
    }
    // outputs[:, 0, :] stays zero (d_out is poisoned; must write everything)
    if (g < R*3) out[((size_t)(b0 + g/3)*SEQ_T + 0)*3 + (g%3)] = 0.0f;
    __syncthreads();

    for (int t = 0; t < SEQ_T-1; t++) {
        float xpf = 0.0f;
        const int pr = g >> 2, pd = g & 3;
        if (g < R*4 && pd < 3 && (t+1) < SEQ_T-1)
            xpf = trg[((size_t)(b0+pr)*SEQ_T + (t+1))*3 + pd];

        // --- dec1 gates ---
        ull acc[R];
#pragma unroll
        for (int r = 0; r < R; r++) {
            const ull* xv = (const ull*)(&xs[r][0]);
            acc[r] = 0ull;
            fma2(acc[r], wx0, xv[0]);
            fma2(acc[r], wx1, xv[1]);
        }
#pragma unroll
        for (int k = 0; k < 16; k++) {
#pragma unroll
            for (int r = 0; r < R; r++) {
                ulonglong2 p = ((const ulonglong2*)(&hs[r][0]))[k];
                fma2(acc[r], wh1[2*k],   p.x);
                fma2(acc[r], wh1[2*k+1], p.y);
            }
        }
#pragma unroll
        for (int r = 0; r < R; r++) {
            float v = hsum(acc[r]) + bb1;
            gact[r][g] = (wg == 2) ? tanh_f(v) : sigm(v);
        }
        __syncthreads();
        {
            float si = gact[rr][jj], sf = gact[rr][64+jj];
            float tg = gact[rr][128+jj], so = gact[rr][192+jj];
            c = sf * c + si * tg;                 // c1
            h1s[rr][jj] = so * tanh_f(c);         // h1
        }
        if (g < R*4 && pd < 3) xs[pr][pd] = xpf;
        __syncthreads();

        // --- dec2 gates: x = h = h1 -> merged weights, K = 64 ---
#pragma unroll
        for (int r = 0; r < R; r++) acc[r] = 0ull;
#pragma unroll
        for (int k = 0; k < 16; k++) {
#pragma unroll
            for (int r = 0; r < R; r++) {
                ulonglong2 p = ((const ulonglong2*)(&h1s[r][0]))[k];
                fma2(acc[r], wd2[2*k],   p.x);
                fma2(acc[r], wd2[2*k+1], p.y);
            }
        }
#pragma unroll
        for (int r = 0; r < R; r++) {
            float v = hsum(acc[r]) + bb2;
            gact[r][g] = (wg == 2) ? tanh_f(v) : sigm(v);
        }
        __syncthreads();
        {
            float si = gact[rr][jj], sf = gact[rr][64+jj];
            float tg = gact[rr][128+jj], so = gact[rr][192+jj];
            c = sf * c + si * tg;                 // c2 (carried)
            hs[rr][jj] = so * tanh_f(c);          // h2 (carried)
        }
        __syncthreads();

        // --- fc: preds[:, t+1, :] = h2 @ fc_W.T + fc_b ---
        if (g < R*3) {
            int r = g / 3, d = g % 3;
            float s = fcbs[d];
#pragma unroll
            for (int j = 0; j < HID; j++)
                s += fcWs[d*HID + j] * hs[r][j];
            out[((size_t)(b0+r)*SEQ_T + (t+1))*3 + d] = s;
        }
    }
}

extern "C" void kernel_launch(void* const* d_in, const int* in_sizes, int n_in,
                              void* d_out, int out_size)
{
    const float* src = (const float*)d_in[0];
    const float* trg = (const float*)d_in[1];

    k_enc1<<<NBLK, 256>>>(src,
                          (const float*)d_in[2],  // enc1_Wih
                          (const float*)d_in[3],  // enc1_Whh
                          (const float*)d_in[4]); // enc1_b
    k_enc2<<<NBLK, 256>>>((const float*)d_in[5],  // enc2_Wih
                          (const float*)d_in[6],  // enc2_Whh
                          (const float*)d_in[7]); // enc2_b
    k_dec <<<NBLK, 256>>>(trg,
                          (const float*)d_in[8],  (const float*)d_in[9],  (const float*)d_in[10],
                          (const float*)d_in[11], (const float*)d_in[12], (const float*)d_in[13],
                          (const float*)d_in[14], (const float*)d_in[15],
                          (float*)d_out);
}

// round 2
// speedup vs baseline: 1.0326x; 1.0326x over previous
#include <cuda_runtime.h>

typedef unsigned long long ull;

#define BATCH 512
#define SEQ_S 1024
#define SEQ_T 512
#define HID   64
#define G4    256
#define R     4
#define NBLK  (BATCH / R)   // 128 CTAs
#define NT    512

// Scratch (device globals: allocation-free rule)
static __device__ float g_y1[(size_t)BATCH * SEQ_S * HID];
static __device__ float g_h[BATCH * HID];
static __device__ float g_c[BATCH * HID];

__device__ __forceinline__ ull pack2(float x, float y) {
    ull r; asm("mov.b64 %0, {%1, %2};" : "=l"(r) : "f"(x), "f"(y)); return r;
}
__device__ __forceinline__ void fma2(ull &acc, ull a, ull b) {
    asm("fma.rn.f32x2 %0, %1, %2, %0;" : "+l"(acc) : "l"(a), "l"(b));
}
__device__ __forceinline__ float hsum(ull a) {
    float x, y; asm("mov.b64 {%0, %1}, %2;" : "=f"(x), "=f"(y) : "l"(a));
    return x + y;
}
__device__ __forceinline__ float sigm(float x) { return 1.0f / (1.0f + __expf(-x)); }
__device__ __forceinline__ float tanh_f(float x) {
    float e = __expf(-2.0f * fabsf(x));
    float r = (1.0f - e) / (1.0f + e);
    return copysignf(r, x);
}

// ---------------------------------------------------------------------------
// Encoder layer 1: x (3-dim) -> y1. 512 threads: gate g = tid&255, K-half =
// tid>>8. Halves combined in smem part[]. c-phase on tid<256.
// ---------------------------------------------------------------------------
__global__ void __launch_bounds__(NT, 1)
k_enc1(const float* __restrict__ src, const float* __restrict__ Wih,
       const float* __restrict__ Whh, const float* __restrict__ bias)
{
    __shared__ __align__(16) float hs[R][HID];
    __shared__ __align__(16) float xs[R][4];
    __shared__ float part[2][R][G4];

    const int tid  = threadIdx.x;
    const int g    = tid & 255;
    const int half = tid >> 8;
    const int b0   = blockIdx.x * R;
    const int rr   = (tid >> 6) & 3, jj = tid & 63;  // c-thread mapping
    const int pid  = tid - 256;                      // prefetch role
    const int pr   = (pid >> 2) & 3, pd = pid & 3;

    ull wh[16];
#pragma unroll
    for (int k = 0; k < 16; k++)
        wh[k] = pack2(Whh[g*HID + half*32 + 2*k], Whh[g*HID + half*32 + 2*k + 1]);
    const ull wx0 = pack2(Wih[g*3+0], Wih[g*3+1]);
    const ull wx1 = pack2(Wih[g*3+2], 0.0f);

    float c = 0.f, bi = 0.f, bf = 0.f, bg = 0.f, bo = 0.f;
    if (tid < 256) {
        bi = bias[jj]; bf = bias[64+jj]; bg = bias[128+jj]; bo = bias[192+jj];
        hs[rr][jj] = 0.f;
    }
    if (pid >= 0 && pid < 16)
        xs[pr][pd] = (pd < 3) ? src[((size_t)(b0+pr)*SEQ_S)*3 + pd] : 0.f;
    __syncthreads();

    for (int t = 0; t < SEQ_S; t++) {
        float xpf = 0.f;
        if (pid >= 0 && pid < 16 && pd < 3 && (t+1) < SEQ_S)
            xpf = src[((size_t)(b0+pr)*SEQ_S + t+1)*3 + pd];

        ull a0 = 0, a1 = 0, a2 = 0, a3 = 0;
        if (half == 0) {
            const ull* x0 = (const ull*)&xs[0][0];
            const ull* x1 = (const ull*)&xs[1][0];
            const ull* x2 = (const ull*)&xs[2][0];
            const ull* x3 = (const ull*)&xs[3][0];
            fma2(a0, wx0, x0[0]); fma2(a0, wx1, x0[1]);
            fma2(a1, wx0, x1[0]); fma2(a1, wx1, x1[1]);
            fma2(a2, wx0, x2[0]); fma2(a2, wx1, x2[1]);
            fma2(a3, wx0, x3[0]); fma2(a3, wx1, x3[1]);
        }
        const ulonglong2* h0 = (const ulonglong2*)&hs[0][half*32];
        const ulonglong2* h1 = (const ulonglong2*)&hs[1][half*32];
        const ulonglong2* h2 = (const ulonglong2*)&hs[2][half*32];
        const ulonglong2* h3 = (const ulonglong2*)&hs[3][half*32];
#pragma unroll
        for (int k = 0; k < 8; k++) {
            ulonglong2 p;
            p = h0[k]; fma2(a0, wh[2*k], p.x); fma2(a0, wh[2*k+1], p.y);
            p = h1[k]; fma2(a1, wh[2*k], p.x); fma2(a1, wh[2*k+1], p.y);
            p = h2[k]; fma2(a2, wh[2*k], p.x); fma2(a2, wh[2*k+1], p.y);
            p = h3[k]; fma2(a3, wh[2*k], p.x); fma2(a3, wh[2*k+1], p.y);
        }
        part[half][0][g] = hsum(a0);
        part[half][1][g] = hsum(a1);
        part[half][2][g] = hsum(a2);
        part[half][3][g] = hsum(a3);
        __syncthreads();

        if (tid < 256) {
            float vi = part[0][rr][jj]      + part[1][rr][jj]      + bi;
            float vf = part[0][rr][64+jj]   + part[1][rr][64+jj]   + bf;
            float vg = part[0][rr][128+jj]  + part[1][rr][128+jj]  + bg;
            float vo = part[0][rr][192+jj]  + part[1][rr][192+jj]  + bo;
            float ii = sigm(vi), ff = sigm(vf), gg = tanh_f(vg), oo = sigm(vo);
            c = ff * c + ii * gg;
            float h = oo * tanh_f(c);
            hs[rr][jj] = h;
            g_y1[((size_t)(b0+rr)*SEQ_S + t)*HID + jj] = h;
        } else if (pid < 16 && pd < 3) {
            xs[pr][pd] = xpf;
        }
        __syncthreads();
    }
}

// ---------------------------------------------------------------------------
// Encoder layer 2: x = y1 (64-dim). Upper 256 threads prefetch next y1 slice.
// ---------------------------------------------------------------------------
__global__ void __launch_bounds__(NT, 1)
k_enc2(const float* __restrict__ Wih, const float* __restrict__ Whh,
       const float* __restrict__ bias)
{
    __shared__ __align__(16) float hs[R][HID];
    __shared__ __align__(16) float xsh[R][HID];
    __shared__ float part[2][R][G4];

    const int tid  = threadIdx.x;
    const int g    = tid & 255;
    const int half = tid >> 8;
    const int b0   = blockIdx.x * R;
    const int rr   = (tid >> 6) & 3, jj = tid & 63;
    const int pid  = tid - 256;
    const int prr  = (pid >> 6) & 3, pjj = pid & 63;

    ull wx[16], wh[16];
#pragma unroll
    for (int k = 0; k < 16; k++) {
        wx[k] = pack2(Wih[g*HID + half*32 + 2*k], Wih[g*HID + half*32 + 2*k + 1]);
        wh[k] = pack2(Whh[g*HID + half*32 + 2*k], Whh[g*HID + half*32 + 2*k + 1]);
    }

    float c = 0.f, bi = 0.f, bf = 0.f, bg = 0.f, bo = 0.f;
    if (tid < 256) {
        bi = bias[jj]; bf = bias[64+jj]; bg = bias[128+jj]; bo = bias[192+jj];
        hs[rr][jj] = 0.f;
    }
    if (pid >= 0)
        xsh[prr][pjj] = g_y1[((size_t)(b0+prr)*SEQ_S)*HID + pjj];
    __syncthreads();

    for (int t = 0; t < SEQ_S; t++) {
        float xpf = 0.f;
        if (pid >= 0 && (t+1) < SEQ_S)
            xpf = g_y1[((size_t)(b0+prr)*SEQ_S + t+1)*HID + pjj];

        ull a0 = 0, a1 = 0, a2 = 0, a3 = 0;
        const ulonglong2* h0 = (const ulonglong2*)&hs[0][half*32];
        const ulonglong2* h1 = (const ulonglong2*)&hs[1][half*32];
        const ulonglong2* h2 = (const ulonglong2*)&hs[2][half*32];
        const ulonglong2* h3 = (const ulonglong2*)&hs[3][half*32];
        const ulonglong2* x0 = (const ulonglong2*)&xsh[0][half*32];
        const ulonglong2* x1 = (const ulonglong2*)&xsh[1][half*32];
        const ulonglong2* x2 = (const ulonglong2*)&xsh[2][half*32];
        const ulonglong2* x3 = (const ulonglong2*)&xsh[3][half*32];
#pragma unroll
        for (int k = 0; k < 8; k++) {
            ulonglong2 p;
            p = h0[k]; fma2(a0, wh[2*k], p.x); fma2(a0, wh[2*k+1], p.y);
            p = h1[k]; fma2(a1, wh[2*k], p.x); fma2(a1, wh[2*k+1], p.y);
            p = h2[k]; fma2(a2, wh[2*k], p.x); fma2(a2, wh[2*k+1], p.y);
            p = h3[k]; fma2(a3, wh[2*k], p.x); fma2(a3, wh[2*k+1], p.y);
            p = x0[k]; fma2(a0, wx[2*k], p.x); fma2(a0, wx[2*k+1], p.y);
            p = x1[k]; fma2(a1, wx[2*k], p.x); fma2(a1, wx[2*k+1], p.y);
            p = x2[k]; fma2(a2, wx[2*k], p.x); fma2(a2, wx[2*k+1], p.y);
            p = x3[k]; fma2(a3, wx[2*k], p.x); fma2(a3, wx[2*k+1], p.y);
        }
        part[half][0][g] = hsum(a0);
        part[half][1][g] = hsum(a1);
        part[half][2][g] = hsum(a2);
        part[half][3][g] = hsum(a3);
        __syncthreads();

        if (tid < 256) {
            float vi = part[0][rr][jj]      + part[1][rr][jj]      + bi;
            float vf = part[0][rr][64+jj]   + part[1][rr][64+jj]   + bf;
            float vg = part[0][rr][128+jj]  + part[1][rr][128+jj]  + bg;
            float vo = part[0][rr][192+jj]  + part[1][rr][192+jj]  + bo;
            float ii = sigm(vi), ff = sigm(vf), gg = tanh_f(vg), oo = sigm(vo);
            c = ff * c + ii * gg;
            hs[rr][jj] = oo * tanh_f(c);
        } else {
            xsh[prr][pjj] = xpf;
        }
        __syncthreads();
    }
    if (tid < 256) {
        g_h[(b0+rr)*HID + jj] = hs[rr][jj];
        g_c[(b0+rr)*HID + jj] = c;
    }
}

// ---------------------------------------------------------------------------
// Decoder: dec1 (x=trg[t]) then dec2 with x=h=h1 -> merged Wd2 = Wih2+Whh2.
// fc epilogue on warp 8 with float4 loads.
// ---------------------------------------------------------------------------
__global__ void __launch_bounds__(NT, 1)
k_dec(const float* __restrict__ trg,
      const float* __restrict__ W1i, const float* __restrict__ W1h, const float* __restrict__ b1,
      const float* __restrict__ W2i, const float* __restrict__ W2h, const float* __restrict__ b2,
      const float* __restrict__ fcW, const float* __restrict__ fcb,
      float* __restrict__ out)
{
    __shared__ __align__(16) float hs[R][HID];
    __shared__ __align__(16) float h1s[R][HID];
    __shared__ __align__(16) float xs[R][4];
    __shared__ float part[2][R][G4];
    __shared__ __align__(16) float fcWs[3*HID];
    __shared__ float fcbs[3];

    const int tid  = threadIdx.x;
    const int g    = tid & 255;
    const int half = tid >> 8;
    const int b0   = blockIdx.x * R;
    const int rr   = (tid >> 6) & 3, jj = tid & 63;
    const int pid  = tid - 256;
    const int pr   = (pid >> 2) & 3, pd = pid & 3;

    ull wh1[16], wd2[16];
#pragma unroll
    for (int k = 0; k < 16; k++) {
        int o = g*HID + half*32 + 2*k;
        wh1[k] = pack2(W1h[o], W1h[o+1]);
        wd2[k] = pack2(W2i[o] + W2h[o], W2i[o+1] + W2h[o+1]);
    }
    const ull wx0 = pack2(W1i[g*3+0], W1i[g*3+1]);
    const ull wx1 = pack2(W1i[g*3+2], 0.0f);

    float c = 0.f;
    float b1i = 0.f, b1f = 0.f, b1g = 0.f, b1o = 0.f;
    float b2i = 0.f, b2f = 0.f, b2g = 0.f, b2o = 0.f;
    if (tid < 256) {
        b1i = b1[jj]; b1f = b1[64+jj]; b1g = b1[128+jj]; b1o = b1[192+jj];
        b2i = b2[jj]; b2f = b2[64+jj]; b2g = b2[128+jj]; b2o = b2[192+jj];
        c = g_c[(b0+rr)*HID + jj];
        hs[rr][jj] = g_h[(b0+rr)*HID + jj];
    }
    if (tid < 3*HID) fcWs[tid] = fcW[tid];
    if (tid < 3)     fcbs[tid] = fcb[tid];
    if (pid >= 0 && pid < 16)
        xs[pr][pd] = (pd < 3) ? trg[((size_t)(b0+pr)*SEQ_T)*3 + pd] : 0.f;
    if (tid < R*3)
        out[((size_t)(b0 + tid/3)*SEQ_T + 0)*3 + (tid%3)] = 0.f;
    __syncthreads();

    for (int t = 0; t < SEQ_T-1; t++) {
        float xpf = 0.f;
        if (pid >= 0 && pid < 16 && pd < 3 && (t+1) < SEQ_T-1)
            xpf = trg[((size_t)(b0+pr)*SEQ_T + t+1)*3 + pd];

        // --- dec1 gates ---
        ull a0 = 0, a1 = 0, a2 = 0, a3 = 0;
        if (half == 0) {
            const ull* x0 = (const ull*)&xs[0][0];
            const ull* x1 = (const ull*)&xs[1][0];
            const ull* x2 = (const ull*)&xs[2][0];
            const ull* x3 = (const ull*)&xs[3][0];
            fma2(a0, wx0, x0[0]); fma2(a0, wx1, x0[1]);
            fma2(a1, wx0, x1[0]); fma2(a1, wx1, x1[1]);
            fma2(a2, wx0, x2[0]); fma2(a2, wx1, x2[1]);
            fma2(a3, wx0, x3[0]); fma2(a3, wx1, x3[1]);
        }
        {
            const ulonglong2* h0 = (const ulonglong2*)&hs[0][half*32];
            const ulonglong2* h1 = (const ulonglong2*)&hs[1][half*32];
            const ulonglong2* h2 = (const ulonglong2*)&hs[2][half*32];
            const ulonglong2* h3 = (const ulonglong2*)&hs[3][half*32];
#pragma unroll
            for (int k = 0; k < 8; k++) {
                ulonglong2 p;
                p = h0[k]; fma2(a0, wh1[2*k], p.x); fma2(a0, wh1[2*k+1], p.y);
                p = h1[k]; fma2(a1, wh1[2*k], p.x); fma2(a1, wh1[2*k+1], p.y);
                p = h2[k]; fma2(a2, wh1[2*k], p.x); fma2(a2, wh1[2*k+1], p.y);
                p = h3[k]; fma2(a3, wh1[2*k], p.x); fma2(a3, wh1[2*k+1], p.y);
            }
        }
        part[half][0][g] = hsum(a0);
        part[half][1][g] = hsum(a1);
        part[half][2][g] = hsum(a2);
        part[half][3][g] = hsum(a3);
        __syncthreads();

        if (tid < 256) {
            float vi = part[0][rr][jj]      + part[1][rr][jj]      + b1i;
            float vf = part[0][rr][64+jj]   + part[1][rr][64+jj]   + b1f;
            float vg = part[0][rr][128+jj]  + part[1][rr][128+jj]  + b1g;
            float vo = part[0][rr][192+jj]  + part[1][rr][192+jj]  + b1o;
            float ii = sigm(vi), ff = sigm(vf), gg = tanh_f(vg), oo = sigm(vo);
            c = ff * c + ii * gg;                  // c1
            h1s[rr][jj] = oo * tanh_f(c);          // h1
        } else if (pid < 16 && pd < 3) {
            xs[pr][pd] = xpf;
        }
        __syncthreads();

        // --- dec2 gates (merged, K=64) ---
        a0 = 0; a1 = 0; a2 = 0; a3 = 0;
        {
            const ulonglong2* h0 = (const ulonglong2*)&h1s[0][half*32];
            const ulonglong2* h1 = (const ulonglong2*)&h1s[1][half*32];
            const ulonglong2* h2 = (const ulonglong2*)&h1s[2][half*32];
            const ulonglong2* h3 = (const ulonglong2*)&h1s[3][half*32];
#pragma unroll
            for (int k = 0; k < 8; k++) {
                ulonglong2 p;
                p = h0[k]; fma2(a0, wd2[2*k], p.x); fma2(a0, wd2[2*k+1], p.y);
                p = h1[k]; fma2(a1, wd2[2*k], p.x); fma2(a1, wd2[2*k+1], p.y);
                p = h2[k]; fma2(a2, wd2[2*k], p.x); fma2(a2, wd2[2*k+1], p.y);
                p = h3[k]; fma2(a3, wd2[2*k], p.x); fma2(a3, wd2[2*k+1], p.y);
            }
        }
        part[half][0][g] = hsum(a0);
        part[half][1][g] = hsum(a1);
        part[half][2][g] = hsum(a2);
        part[half][3][g] = hsum(a3);
        __syncthreads();

        if (tid < 256) {
            float vi = part[0][rr][jj]      + part[1][rr][jj]      + b2i;
            float vf = part[0][rr][64+jj]   + part[1][rr][64+jj]   + b2f;
            float vg = part[0][rr][128+jj]  + part[1][rr][128+jj]  + b2g;
            float vo = part[0][rr][192+jj]  + part[1][rr][192+jj]  + b2o;
            float ii = sigm(vi), ff = sigm(vf), gg = tanh_f(vg), oo = sigm(vo);
            c = ff * c + ii * gg;                  // c2 (carried)
            hs[rr][jj] = oo * tanh_f(c);           // h2 (carried)
        }
        __syncthreads();

        // --- fc: preds[:, t+1, :] = h2 @ fc_W.T + fc_b  (warp 8) ---
        if (pid >= 0 && pid < 12) {
            int r = pid / 3, d = pid % 3;
            const float4* w4 = (const float4*)&fcWs[d*HID];
            const float4* h4 = (const float4*)&hs[r][0];
            float s = fcbs[d];
#pragma unroll
            for (int k2 = 0; k2 < 16; k2++) {
                float4 a = w4[k2], b = h4[k2];
                s += a.x*b.x + a.y*b.y + a.z*b.z + a.w*b.w;
            }
            out[((size_t)(b0+r)*SEQ_T + t+1)*3 + d] = s;
        }
    }
}

extern "C" void kernel_launch(void* const* d_in, const int* in_sizes, int n_in,
                              void* d_out, int out_size)
{
    const float* src = (const float*)d_in[0];
    const float* trg = (const float*)d_in[1];

    k_enc1<<<NBLK, NT>>>(src,
                         (const float*)d_in[2],
                         (const float*)d_in[3],
                         (const float*)d_in[4]);
    k_enc2<<<NBLK, NT>>>((const float*)d_in[5],
                         (const float*)d_in[6],
                         (const float*)d_in[7]);
    k_dec <<<NBLK, NT>>>(trg,
                         (const float*)d_in[8],  (const float*)d_in[9],  (const float*)d_in[10],
                         (const float*)d_in[11], (const float*)d_in[12], (const float*)d_in[13],
                         (const float*)d_in[14], (const float*)d_in[15],
                         (float*)d_out);
}